// round 14
// baseline (speedup 1.0000x reference)
#include <cuda_runtime.h>
#include <math.h>
#include <stdint.h>

#define NATOMS 10000
#define NPAIR  100000

typedef unsigned long long u64;
__device__ __forceinline__ u64 pk2(float a, float b) {
    u64 r; asm("mov.b64 %0,{%1,%2};" : "=l"(r) : "f"(a), "f"(b)); return r;
}
__device__ __forceinline__ void up2(u64 v, float& a, float& b) {
    asm("mov.b64 {%0,%1},%2;" : "=f"(a), "=f"(b) : "l"(v));
}
__device__ __forceinline__ u64 fma2(u64 a, u64 b, u64 c) {
    u64 d; asm("fma.rn.f32x2 %0,%1,%2,%3;" : "=l"(d) : "l"(a), "l"(b), "l"(c)); return d;
}
__device__ __forceinline__ uint32_t f2tf32(float x) {
    uint32_t r; asm("cvt.rna.tf32.f32 %0, %1;" : "=r"(r) : "f"(x)); return r;
}
#define MMA_TF32(c0,c1,c2,c3,a0,a1,a2,a3,b0,b1) \
    asm volatile("mma.sync.aligned.m16n8k8.row.col.f32.tf32.tf32.f32 " \
        "{%0,%1,%2,%3}, {%4,%5,%6,%7}, {%8,%9}, {%0,%1,%2,%3};" \
        : "+f"(c0), "+f"(c1), "+f"(c2), "+f"(c3) \
        : "r"(a0), "r"(a1), "r"(a2), "r"(a3), "r"(b0), "r"(b1))

// Scratch (static device allocations — allowed). 16B-aligned.
__device__ __align__(16) float d_Q   [NATOMS * 384];
__device__ __align__(16) float d_Kb  [NATOMS * 384];
__device__ __align__(16) float d_P   [NATOMS * 512];
__device__ __align__(16) float d_alpha[(size_t)NPAIR * 12];
__device__ __align__(16) float d_wij [(size_t)NPAIR * 384];   // 153.6 MB scratch
__device__ __align__(16) uint32_t d_Whi[32 * 384];
__device__ __align__(16) uint32_t d_Wlo[32 * 384];
__device__ int d_rowstart[NATOMS + 1];

__global__ void dummy_kernel() {}

// ---------------------------------------------------------------------------
// rowstart + Wf2 tf32 split (fused prep utilities).
// ---------------------------------------------------------------------------
__global__ __launch_bounds__(256) void rowstart_kernel(
    const int* __restrict__ idx_i, const float* __restrict__ Wf2)
{
    int p = blockIdx.x * 256 + threadIdx.x;
    if (p < 32 * 384) {
        float w = Wf2[p];
        uint32_t hi = f2tf32(w);
        d_Whi[p] = hi;
        d_Wlo[p] = f2tf32(w - __uint_as_float(hi));
    }
    if (p >= NPAIR) return;
    int ip   = idx_i[p];
    int prev = (p == 0) ? -1 : idx_i[p - 1];
    for (int a = prev + 1; a <= ip; a++) d_rowstart[a] = p;
    if (p == NPAIR - 1)
        for (int a = ip + 1; a <= NATOMS; a++) d_rowstart[a] = NPAIR;
}

// ---------------------------------------------------------------------------
// Fused per-atom prep (unchanged; measured 53.6 us).
// ---------------------------------------------------------------------------
__global__ __launch_bounds__(256) void prep_kernel(
    const float* __restrict__ x,    const float* __restrict__ W_in,
    const float* __restrict__ b_in,
    const float* __restrict__ WQ,   const float* __restrict__ WK,
    const float* __restrict__ W_out)
{
    __shared__ __align__(16) float sx[32][128];
    union __align__(16) UB {
        float w[32][128];
        float qk[2][2][32][36];
    };
    __shared__ UB sb;

    int tid  = threadIdx.x;
    int wid  = tid >> 5, lane = tid & 31;
    int a0   = blockIdx.x * 32;

#pragma unroll
    for (int t = 0; t < 4; t++) {
        int p = tid + t * 256;
        int row = p >> 5, c4 = p & 31;
        float4 v = make_float4(0.f, 0.f, 0.f, 0.f);
        if (a0 + row < NATOMS)
            v = *(const float4*)(x + (size_t)(a0 + row) * 128 + c4 * 4);
        *(float4*)&sx[row][c4 * 4] = v;
    }

    float4 wr[4];
#pragma unroll
    for (int t = 0; t < 4; t++) {
        int p = tid + t * 256;
        wr[t] = *(const float4*)(W_in + (size_t)(p >> 5) * 128 + (p & 31) * 4);
    }
    u64 acc2[4][2];
#pragma unroll
    for (int i = 0; i < 4; i++) { acc2[i][0] = 0ull; acc2[i][1] = 0ull; }

    for (int kk = 0; kk < 128; kk += 32) {
        __syncthreads();
#pragma unroll
        for (int t = 0; t < 4; t++) {
            int p = tid + t * 256;
            *(float4*)&sb.w[p >> 5][(p & 31) * 4] = wr[t];
        }
        __syncthreads();
        if (kk < 96) {
#pragma unroll
            for (int t = 0; t < 4; t++) {
                int p = tid + t * 256;
                wr[t] = *(const float4*)(W_in + (size_t)(kk + 32 + (p >> 5)) * 128
                                         + (p & 31) * 4);
            }
        }
#pragma unroll
        for (int k4 = 0; k4 < 8; k4++) {
            float av[4][4];
#pragma unroll
            for (int i = 0; i < 4; i++) {
                float4 a4 = *(float4*)&sx[wid * 4 + i][kk + k4 * 4];
                av[i][0] = a4.x; av[i][1] = a4.y; av[i][2] = a4.z; av[i][3] = a4.w;
            }
#pragma unroll
            for (int k = 0; k < 4; k++) {
                float4 b = *(float4*)&sb.w[k4 * 4 + k][lane * 4];
                u64 b01 = pk2(b.x, b.y), b23 = pk2(b.z, b.w);
#pragma unroll
                for (int i = 0; i < 4; i++) {
                    u64 a2 = pk2(av[i][k], av[i][k]);
                    acc2[i][0] = fma2(a2, b01, acc2[i][0]);
                    acc2[i][1] = fma2(a2, b23, acc2[i][1]);
                }
            }
        }
    }
    __syncwarp();
    {
        float4 bb = *(const float4*)(b_in + lane * 4);
#pragma unroll
        for (int i = 0; i < 4; i++) {
            float v0, v1, v2, v3;
            up2(acc2[i][0], v0, v1);
            up2(acc2[i][1], v2, v3);
            float4 v = make_float4(v0 + bb.x, v1 + bb.y, v2 + bb.z, v3 + bb.w);
            *(float4*)&sx[wid * 4 + i][lane * 4] = v;
        }
    }
    __syncwarp();

    float4 qr[4];
#pragma unroll
    for (int t = 0; t < 4; t++) {
        int e = (tid + t * 256) * 4;
        const float* src = (e >> 11) ? WK : WQ;
        int rem = e & 2047;
        qr[t] = *(const float4*)(src + (rem >> 10) * 1024 + (rem & 1023));
    }
    for (int r = 0; r < 6; r++) {
        __syncthreads();
#pragma unroll
        for (int t = 0; t < 4; t++) {
            int e = (tid + t * 256) * 4;
            int sel = e >> 11, rem = e & 2047;
            int dhp = rem >> 10, w = rem & 1023;
            *(float4*)&sb.qk[sel][dhp][w >> 5][w & 31] = qr[t];
        }
        __syncthreads();
        if (r < 5) {
#pragma unroll
            for (int t = 0; t < 4; t++) {
                int e = (tid + t * 256) * 4;
                const float* src = (e >> 11) ? WK : WQ;
                int rem = e & 2047;
                qr[t] = *(const float4*)(src + (size_t)(2 * (r + 1) + (rem >> 10)) * 1024
                                         + (rem & 1023));
            }
        }
#pragma unroll
        for (int u = 0; u < 2; u++) {
            int dh = 2 * r + u, h = dh & 3;
            u64 qa2[4] = {0ull, 0ull, 0ull, 0ull};
            u64 ka2[4] = {0ull, 0ull, 0ull, 0ull};
#pragma unroll
            for (int j4 = 0; j4 < 8; j4++) {
                float4 wq = *(float4*)&sb.qk[0][u][lane][j4 * 4];
                float4 wk = *(float4*)&sb.qk[1][u][lane][j4 * 4];
                u64 wq01 = pk2(wq.x, wq.y), wq23 = pk2(wq.z, wq.w);
                u64 wk01 = pk2(wk.x, wk.y), wk23 = pk2(wk.z, wk.w);
#pragma unroll
                for (int rr = 0; rr < 4; rr++) {
                    float4 xv = *(float4*)&sx[wid * 4 + rr][h * 32 + j4 * 4];
                    u64 x01 = pk2(xv.x, xv.y), x23 = pk2(xv.z, xv.w);
                    qa2[rr] = fma2(x01, wq01, qa2[rr]);
                    qa2[rr] = fma2(x23, wq23, qa2[rr]);
                    ka2[rr] = fma2(x01, wk01, ka2[rr]);
                    ka2[rr] = fma2(x23, wk23, ka2[rr]);
                }
            }
#pragma unroll
            for (int rr = 0; rr < 4; rr++) {
                int a = a0 + wid * 4 + rr;
                if (a < NATOMS) {
                    float qlo, qhi, klo, khi;
                    up2(qa2[rr], qlo, qhi);
                    up2(ka2[rr], klo, khi);
                    d_Q [(size_t)a * 384 + dh * 32 + lane] = qlo + qhi;
                    d_Kb[(size_t)a * 384 + dh * 32 + lane] = klo + khi;
                }
            }
        }
    }

    float4 pr[4];
#pragma unroll
    for (int t = 0; t < 4; t++) {
        int p = tid + t * 256;
        pr[t] = *(const float4*)(W_out + (size_t)(p >> 5) * 128 + (p & 31) * 4);
    }
    for (int h = 0; h < 4; h++) {
        __syncthreads();
#pragma unroll
        for (int t = 0; t < 4; t++) {
            int p = tid + t * 256;
            *(float4*)&sb.w[p >> 5][(p & 31) * 4] = pr[t];
        }
        __syncthreads();
        if (h < 3) {
#pragma unroll
            for (int t = 0; t < 4; t++) {
                int p = tid + t * 256;
                pr[t] = *(const float4*)(W_out + (size_t)((h + 1) * 32 + (p >> 5)) * 128
                                         + (p & 31) * 4);
            }
        }
        u64 pa2[4][2];
#pragma unroll
        for (int i = 0; i < 4; i++) { pa2[i][0] = 0ull; pa2[i][1] = 0ull; }
#pragma unroll
        for (int k4 = 0; k4 < 8; k4++) {
            float av[4][4];
#pragma unroll
            for (int i = 0; i < 4; i++) {
                float4 a4 = *(float4*)&sx[wid * 4 + i][h * 32 + k4 * 4];
                av[i][0] = a4.x; av[i][1] = a4.y; av[i][2] = a4.z; av[i][3] = a4.w;
            }
#pragma unroll
            for (int k = 0; k < 4; k++) {
                float4 b = *(float4*)&sb.w[k4 * 4 + k][lane * 4];
                u64 b01 = pk2(b.x, b.y), b23 = pk2(b.z, b.w);
#pragma unroll
                for (int i = 0; i < 4; i++) {
                    u64 a2 = pk2(av[i][k], av[i][k]);
                    pa2[i][0] = fma2(a2, b01, pa2[i][0]);
                    pa2[i][1] = fma2(a2, b23, pa2[i][1]);
                }
            }
        }
#pragma unroll
        for (int i = 0; i < 4; i++) {
            int a = a0 + wid * 4 + i;
            if (a < NATOMS) {
                float v0, v1, v2, v3;
                up2(pa2[i][0], v0, v1);
                up2(pa2[i][1], v2, v3);
                *(float4*)&d_P[(size_t)a * 512 + h * 128 + lane * 4] =
                    make_float4(v0, v1, v2, v3);
            }
        }
    }
}

// ---------------------------------------------------------------------------
// wij_kernel: Wij[p, 384] = ssp(rbf@Wf1+bf1) @ Wf2 + bf2, tf32 3-pass MMA.
// Warp = 16-pair tile (6250 tiles). Fragment mappings verified in R11.
// B-fragments via __ldg from pre-split d_Whi/d_Wlo (L1-resident, 96 KB).
// ---------------------------------------------------------------------------
__global__ __launch_bounds__(256) void wij_kernel(
    const float* __restrict__ rbf, const float* __restrict__ Wf1,
    const float* __restrict__ bf1, const float* __restrict__ bf2)
{
    __shared__ float sWf1[32][33];
    __shared__ uint32_t shi[8][16][36];
    __shared__ uint32_t slo[8][16][36];

    int tid  = threadIdx.x;
    int wid  = tid >> 5, lane = tid & 31;
    int grp  = lane >> 2, tg = lane & 3;

    for (int t = tid; t < 1024; t += 256) sWf1[t >> 5][t & 31] = Wf1[t];
    float bf1v = bf1[lane];
    __syncthreads();

    int tile = blockIdx.x * 8 + wid;
    if (tile >= NPAIR / 16) return;
    int p0 = tile * 16;

    // ---- h1 for 16 pairs: shfl-dot, ssp, tf32 split ----
#pragma unroll 4
    for (int t = 0; t < 16; t++) {
        float rv = rbf[(size_t)(p0 + t) * 32 + lane];
        float acc = bf1v;
#pragma unroll
        for (int r = 0; r < 32; r++)
            acc += __shfl_sync(0xffffffffu, rv, r) * sWf1[r][lane];
        float sp = (acc > 20.f) ? acc : log1pf(expf(acc));
        float h = sp - 0.69314718055994531f;
        uint32_t hi = f2tf32(h);
        shi[wid][t][lane] = hi;
        slo[wid][t][lane] = f2tf32(h - __uint_as_float(hi));
    }
    __syncwarp();

    // ---- A fragments for all 4 k-slices (R11-verified mapping) ----
    uint32_t ah[4][4], al[4][4];
#pragma unroll
    for (int ks = 0; ks < 4; ks++) {
        int kk = ks * 8;
        ah[ks][0] = shi[wid][grp][kk + tg];
        ah[ks][1] = shi[wid][grp + 8][kk + tg];
        ah[ks][2] = shi[wid][grp][kk + tg + 4];
        ah[ks][3] = shi[wid][grp + 8][kk + tg + 4];
        al[ks][0] = slo[wid][grp][kk + tg];
        al[ks][1] = slo[wid][grp + 8][kk + tg];
        al[ks][2] = slo[wid][grp][kk + tg + 4];
        al[ks][3] = slo[wid][grp + 8][kk + tg + 4];
    }

#pragma unroll
    for (int chunk = 0; chunk < 3; chunk++) {
        float c[16][4];
#pragma unroll
        for (int n = 0; n < 16; n++)
#pragma unroll
            for (int j = 0; j < 4; j++) c[n][j] = 0.f;

#pragma unroll
        for (int n = 0; n < 16; n++) {
            int f = chunk * 128 + n * 8 + grp;
#pragma unroll
            for (int ks = 0; ks < 4; ks++) {
                int kk = ks * 8;
                uint32_t bh0 = __ldg(&d_Whi[(kk + tg) * 384 + f]);
                uint32_t bh1 = __ldg(&d_Whi[(kk + tg + 4) * 384 + f]);
                uint32_t bl0 = __ldg(&d_Wlo[(kk + tg) * 384 + f]);
                uint32_t bl1 = __ldg(&d_Wlo[(kk + tg + 4) * 384 + f]);
                MMA_TF32(c[n][0], c[n][1], c[n][2], c[n][3],
                         ah[ks][0], ah[ks][1], ah[ks][2], ah[ks][3], bh0, bh1);
                MMA_TF32(c[n][0], c[n][1], c[n][2], c[n][3],
                         ah[ks][0], ah[ks][1], ah[ks][2], ah[ks][3], bl0, bl1);
                MMA_TF32(c[n][0], c[n][1], c[n][2], c[n][3],
                         al[ks][0], al[ks][1], al[ks][2], al[ks][3], bh0, bh1);
            }
        }
        // ---- store (+bf2): C layout row grp / grp+8, cols n*8+2tg,+1 ----
#pragma unroll
        for (int n = 0; n < 16; n++) {
            int col = chunk * 128 + n * 8 + 2 * tg;
            float b2a = __ldg(&bf2[col]), b2b = __ldg(&bf2[col + 1]);
            float2 v0 = make_float2(c[n][0] + b2a, c[n][1] + b2b);
            float2 v1 = make_float2(c[n][2] + b2a, c[n][3] + b2b);
            *(float2*)&d_wij[(size_t)(p0 + grp) * 384 + col]     = v0;
            *(float2*)&d_wij[(size_t)(p0 + grp + 8) * 384 + col] = v1;
        }
    }
}

// ---------------------------------------------------------------------------
// contract_kernel: alpha = scale * sum_f (Q_i*K_j) * Wij. R8's proven
// gather+butterfly skeleton, wacc loop replaced by streamed Wij loads.
// ---------------------------------------------------------------------------
__global__ __launch_bounds__(256, 2) void contract_kernel(
    const float* __restrict__ phi,  const float* __restrict__ pmask,
    const int*   __restrict__ idx_i, const int* __restrict__ idx_j)
{
    int tid  = threadIdx.x;
    int lane = tid & 31;
    int warp  = blockIdx.x * 8 + (tid >> 5);
    int nwarp = gridDim.x * 8;

    for (int pb = warp * 4; pb < NPAIR; pb += nwarp * 4) {
        // ---- hoisted: e = Q_i*K_j (L2 gathers), wv = Wij (HBM stream) ----
        float e[4][12], wv[4][12], scale[4];
#pragma unroll
        for (int q = 0; q < 4; q++) {
            int p  = pb + q;
            int ii = idx_i[p], jj = idx_j[p];
            const float* Qr = &d_Q  [(size_t)ii * 384 + lane];
            const float* Kr = &d_Kb [(size_t)jj * 384 + lane];
            const float* Wr = &d_wij[(size_t)p  * 384 + lane];
#pragma unroll
            for (int d = 0; d < 12; d++) {
                e[q][d]  = Qr[d * 32] * Kr[d * 32];
                wv[q][d] = Wr[d * 32];
            }
            float m = pmask[p];
            scale[q] = phi[p] * m * m * m * 0.17677669529663687f;
        }
        // ---- reduce (R8-proven butterflies) ----
#pragma unroll
        for (int q = 0; q < 4; q++) {
            float my = 0.f;
#pragma unroll
            for (int d = 0; d < 12; d++) {
                float partial = e[q][d] * wv[q][d];
#pragma unroll
                for (int o = 16; o > 0; o >>= 1)
                    partial += __shfl_xor_sync(0xffffffffu, partial, o);
                if (lane == d) my = partial * scale[q];
            }
            if (lane < 12) d_alpha[(size_t)(pb + q) * 12 + lane] = my;
        }
    }
}

// ---------------------------------------------------------------------------
// agg: R12/R13 form (rowstart; measured ~55-58 us with rowstart).
// ---------------------------------------------------------------------------
__global__ __launch_bounds__(128) void agg_kernel(
    const int*   __restrict__ idx_j,
    const float* __restrict__ sph,   const float* __restrict__ b_out,
    float* __restrict__ out)
{
    int atom = blockIdx.x;
    int c    = threadIdx.x;
    __shared__ float sal[2][12];
    __shared__ float ssph[2][16];

    int p0 = d_rowstart[atom];
    int p1 = d_rowstart[atom + 1];

    float acc[15];
#pragma unroll
    for (int m = 0; m < 15; m++) acc[m] = 0.f;

    float pv0 = 0.f, pv1 = 0.f, pv2 = 0.f, pv3 = 0.f;
    if (p0 < p1) {
        int j0 = idx_j[p0];
        const float* Pr = &d_P[(size_t)j0 * 512 + c];
        pv0 = Pr[0]; pv1 = Pr[128]; pv2 = Pr[256]; pv3 = Pr[384];
        if (c < 12)                 sal[0][c]     = d_alpha[(size_t)p0 * 12 + c];
        else if (c >= 32 && c < 47) ssph[0][c-32] = sph[(size_t)p0 * 15 + (c - 32)];
    }
    __syncthreads();

    for (int p = p0; p < p1; p++) {
        int b  = (p - p0) & 1;
        int nb = b ^ 1;
        if (p + 1 < p1) {
            if (c < 12)                 sal[nb][c]     = d_alpha[(size_t)(p+1) * 12 + c];
            else if (c >= 32 && c < 47) ssph[nb][c-32] = sph[(size_t)(p+1) * 15 + (c - 32)];
        }
        int jn = (p + 1 < p1) ? idx_j[p + 1] : 0;
        const float* Pn = &d_P[(size_t)jn * 512 + c];
        float n0 = Pn[0], n1 = Pn[128], n2 = Pn[256], n3 = Pn[384];

        float e0 = sal[b][0]*pv0 + sal[b][1]*pv1 + sal[b][2] *pv2 + sal[b][3] *pv3;
        float e1 = sal[b][4]*pv0 + sal[b][5]*pv1 + sal[b][6] *pv2 + sal[b][7] *pv3;
        float e2 = sal[b][8]*pv0 + sal[b][9]*pv1 + sal[b][10]*pv2 + sal[b][11]*pv3;
        acc[0]  += ssph[b][0]  * e0;
        acc[1]  += ssph[b][1]  * e0;
        acc[2]  += ssph[b][2]  * e0;
        acc[3]  += ssph[b][3]  * e1;
        acc[4]  += ssph[b][4]  * e1;
        acc[5]  += ssph[b][5]  * e1;
        acc[6]  += ssph[b][6]  * e1;
        acc[7]  += ssph[b][7]  * e1;
        acc[8]  += ssph[b][8]  * e2;
        acc[9]  += ssph[b][9]  * e2;
        acc[10] += ssph[b][10] * e2;
        acc[11] += ssph[b][11] * e2;
        acc[12] += ssph[b][12] * e2;
        acc[13] += ssph[b][13] * e2;
        acc[14] += ssph[b][14] * e2;
        __syncthreads();
        pv0 = n0; pv1 = n1; pv2 = n2; pv3 = n3;
    }

    float bo = b_out[c];
#pragma unroll
    for (int m = 0; m < 15; m++)
        out[((size_t)atom * 15 + m) * 128 + c] = acc[m] + bo;
}

// ---------------------------------------------------------------------------
extern "C" void kernel_launch(void* const* d_in, const int* in_sizes, int n_in,
                              void* d_out, int out_size)
{
    const float* x     = (const float*)d_in[0];
    const float* rbf   = (const float*)d_in[1];
    const float* sph   = (const float*)d_in[2];
    const float* phi   = (const float*)d_in[3];
    const int*   idx_i = (const int*)  d_in[4];
    const int*   idx_j = (const int*)  d_in[5];
    const float* pmask = (const float*)d_in[6];
    const float* WQ    = (const float*)d_in[7];
    const float* WK    = (const float*)d_in[8];
    const float* W_in  = (const float*)d_in[9];
    const float* b_in  = (const float*)d_in[10];
    const float* Wf1   = (const float*)d_in[11];
    const float* bf1   = (const float*)d_in[12];
    const float* Wf2   = (const float*)d_in[13];
    const float* bf2   = (const float*)d_in[14];
    const float* W_out = (const float*)d_in[15];
    const float* b_out = (const float*)d_in[16];
    float* out = (float*)d_out;

    // Capture = our 4th launch -> wij_kernel (the new MMA GEMM).
    dummy_kernel<<<1, 32>>>();                                     // 1
    rowstart_kernel<<<(NPAIR + 255) / 256, 256>>>(idx_i, Wf2);     // 2
    prep_kernel<<<(NATOMS + 31) / 32, 256>>>(x, W_in, b_in, WQ, WK, W_out); // 3
    wij_kernel<<<(NPAIR / 16 + 7) / 8, 256>>>(rbf, Wf1, bf1, bf2); // 4 <- profiled
    contract_kernel<<<296, 256>>>(phi, pmask, idx_i, idx_j);       // 5
    agg_kernel<<<NATOMS, 128>>>(idx_j, sph, b_out, out);           // 6
}

// round 15
// speedup vs baseline: 1.5872x; 1.5872x over previous
#include <cuda_runtime.h>
#include <math.h>

#define NATOMS 10000
#define NPAIR  100000
#define PREP_BLOCKS ((NATOMS + 31) / 32)              // 313
#define ROWSTART_BLOCKS ((NPAIR + 255) / 256)         // 391

typedef unsigned long long u64;
__device__ __forceinline__ u64 pk2(float a, float b) {
    u64 r; asm("mov.b64 %0,{%1,%2};" : "=l"(r) : "f"(a), "f"(b)); return r;
}
__device__ __forceinline__ void up2(u64 v, float& a, float& b) {
    asm("mov.b64 {%0,%1},%2;" : "=f"(a), "=f"(b) : "l"(v));
}
__device__ __forceinline__ u64 fma2(u64 a, u64 b, u64 c) {
    u64 d; asm("fma.rn.f32x2 %0,%1,%2,%3;" : "=l"(d) : "l"(a), "l"(b), "l"(c)); return d;
}

// Scratch (static device allocations — allowed). 16B-aligned.
__device__ __align__(16) float d_Q   [NATOMS * 384];
__device__ __align__(16) float d_Kb  [NATOMS * 384];
__device__ __align__(16) float d_P   [NATOMS * 512];
__device__ __align__(16) float d_alpha[(size_t)NPAIR * 12];
__device__ int d_rowstart[NATOMS + 1];

// ---------------------------------------------------------------------------
// prep_kernel: blocks [0, 313) do the fused per-atom prep (measured 53.6 us);
// blocks [313, 704) do the rowstart scatter (fused to save a launch).
// ---------------------------------------------------------------------------
__global__ __launch_bounds__(256) void prep_kernel(
    const float* __restrict__ x,    const float* __restrict__ W_in,
    const float* __restrict__ b_in,
    const float* __restrict__ WQ,   const float* __restrict__ WK,
    const float* __restrict__ W_out, const int* __restrict__ idx_i)
{
    __shared__ __align__(16) float sx[32][128];
    union __align__(16) UB {
        float w[32][128];
        float qk[2][2][32][36];
    };
    __shared__ UB sb;

    int tid  = threadIdx.x;

    if (blockIdx.x >= PREP_BLOCKS) {
        // ---- rowstart scatter (idx_i sorted) ----
        int p = (blockIdx.x - PREP_BLOCKS) * 256 + tid;
        if (p >= NPAIR) return;
        int ip   = idx_i[p];
        int prev = (p == 0) ? -1 : idx_i[p - 1];
        for (int a = prev + 1; a <= ip; a++) d_rowstart[a] = p;
        if (p == NPAIR - 1)
            for (int a = ip + 1; a <= NATOMS; a++) d_rowstart[a] = NPAIR;
        return;
    }

    int wid  = tid >> 5, lane = tid & 31;
    int a0   = blockIdx.x * 32;

#pragma unroll
    for (int t = 0; t < 4; t++) {
        int p = tid + t * 256;
        int row = p >> 5, c4 = p & 31;
        float4 v = make_float4(0.f, 0.f, 0.f, 0.f);
        if (a0 + row < NATOMS)
            v = *(const float4*)(x + (size_t)(a0 + row) * 128 + c4 * 4);
        *(float4*)&sx[row][c4 * 4] = v;
    }

    // ---- Phase 1: xh = x @ W_in + b ----
    float4 wr[4];
#pragma unroll
    for (int t = 0; t < 4; t++) {
        int p = tid + t * 256;
        wr[t] = *(const float4*)(W_in + (size_t)(p >> 5) * 128 + (p & 31) * 4);
    }
    u64 acc2[4][2];
#pragma unroll
    for (int i = 0; i < 4; i++) { acc2[i][0] = 0ull; acc2[i][1] = 0ull; }

    for (int kk = 0; kk < 128; kk += 32) {
        __syncthreads();
#pragma unroll
        for (int t = 0; t < 4; t++) {
            int p = tid + t * 256;
            *(float4*)&sb.w[p >> 5][(p & 31) * 4] = wr[t];
        }
        __syncthreads();
        if (kk < 96) {
#pragma unroll
            for (int t = 0; t < 4; t++) {
                int p = tid + t * 256;
                wr[t] = *(const float4*)(W_in + (size_t)(kk + 32 + (p >> 5)) * 128
                                         + (p & 31) * 4);
            }
        }
#pragma unroll
        for (int k4 = 0; k4 < 8; k4++) {
            float av[4][4];
#pragma unroll
            for (int i = 0; i < 4; i++) {
                float4 a4 = *(float4*)&sx[wid * 4 + i][kk + k4 * 4];
                av[i][0] = a4.x; av[i][1] = a4.y; av[i][2] = a4.z; av[i][3] = a4.w;
            }
#pragma unroll
            for (int k = 0; k < 4; k++) {
                float4 b = *(float4*)&sb.w[k4 * 4 + k][lane * 4];
                u64 b01 = pk2(b.x, b.y), b23 = pk2(b.z, b.w);
#pragma unroll
                for (int i = 0; i < 4; i++) {
                    u64 a2 = pk2(av[i][k], av[i][k]);
                    acc2[i][0] = fma2(a2, b01, acc2[i][0]);
                    acc2[i][1] = fma2(a2, b23, acc2[i][1]);
                }
            }
        }
    }
    __syncwarp();
    {
        float4 bb = *(const float4*)(b_in + lane * 4);
#pragma unroll
        for (int i = 0; i < 4; i++) {
            float v0, v1, v2, v3;
            up2(acc2[i][0], v0, v1);
            up2(acc2[i][1], v2, v3);
            float4 v = make_float4(v0 + bb.x, v1 + bb.y, v2 + bb.z, v3 + bb.w);
            *(float4*)&sx[wid * 4 + i][lane * 4] = v;
        }
    }
    __syncwarp();

    // ---- Phase 2: Q,K — 6 rounds of 2 dh ----
    float4 qr[4];
#pragma unroll
    for (int t = 0; t < 4; t++) {
        int e = (tid + t * 256) * 4;
        const float* src = (e >> 11) ? WK : WQ;
        int rem = e & 2047;
        qr[t] = *(const float4*)(src + (rem >> 10) * 1024 + (rem & 1023));
    }
    for (int r = 0; r < 6; r++) {
        __syncthreads();
#pragma unroll
        for (int t = 0; t < 4; t++) {
            int e = (tid + t * 256) * 4;
            int sel = e >> 11, rem = e & 2047;
            int dhp = rem >> 10, w = rem & 1023;
            *(float4*)&sb.qk[sel][dhp][w >> 5][w & 31] = qr[t];
        }
        __syncthreads();
        if (r < 5) {
#pragma unroll
            for (int t = 0; t < 4; t++) {
                int e = (tid + t * 256) * 4;
                const float* src = (e >> 11) ? WK : WQ;
                int rem = e & 2047;
                qr[t] = *(const float4*)(src + (size_t)(2 * (r + 1) + (rem >> 10)) * 1024
                                         + (rem & 1023));
            }
        }
#pragma unroll
        for (int u = 0; u < 2; u++) {
            int dh = 2 * r + u, h = dh & 3;
            u64 qa2[4] = {0ull, 0ull, 0ull, 0ull};
            u64 ka2[4] = {0ull, 0ull, 0ull, 0ull};
#pragma unroll
            for (int j4 = 0; j4 < 8; j4++) {
                float4 wq = *(float4*)&sb.qk[0][u][lane][j4 * 4];
                float4 wk = *(float4*)&sb.qk[1][u][lane][j4 * 4];
                u64 wq01 = pk2(wq.x, wq.y), wq23 = pk2(wq.z, wq.w);
                u64 wk01 = pk2(wk.x, wk.y), wk23 = pk2(wk.z, wk.w);
#pragma unroll
                for (int rr = 0; rr < 4; rr++) {
                    float4 xv = *(float4*)&sx[wid * 4 + rr][h * 32 + j4 * 4];
                    u64 x01 = pk2(xv.x, xv.y), x23 = pk2(xv.z, xv.w);
                    qa2[rr] = fma2(x01, wq01, qa2[rr]);
                    qa2[rr] = fma2(x23, wq23, qa2[rr]);
                    ka2[rr] = fma2(x01, wk01, ka2[rr]);
                    ka2[rr] = fma2(x23, wk23, ka2[rr]);
                }
            }
#pragma unroll
            for (int rr = 0; rr < 4; rr++) {
                int a = a0 + wid * 4 + rr;
                if (a < NATOMS) {
                    float qlo, qhi, klo, khi;
                    up2(qa2[rr], qlo, qhi);
                    up2(ka2[rr], klo, khi);
                    d_Q [(size_t)a * 384 + dh * 32 + lane] = qlo + qhi;
                    d_Kb[(size_t)a * 384 + dh * 32 + lane] = klo + khi;
                }
            }
        }
    }

    // ---- Phase 3: P = xh_head @ W_out block, per head ----
    float4 pr[4];
#pragma unroll
    for (int t = 0; t < 4; t++) {
        int p = tid + t * 256;
        pr[t] = *(const float4*)(W_out + (size_t)(p >> 5) * 128 + (p & 31) * 4);
    }
    for (int h = 0; h < 4; h++) {
        __syncthreads();
#pragma unroll
        for (int t = 0; t < 4; t++) {
            int p = tid + t * 256;
            *(float4*)&sb.w[p >> 5][(p & 31) * 4] = pr[t];
        }
        __syncthreads();
        if (h < 3) {
#pragma unroll
            for (int t = 0; t < 4; t++) {
                int p = tid + t * 256;
                pr[t] = *(const float4*)(W_out + (size_t)((h + 1) * 32 + (p >> 5)) * 128
                                         + (p & 31) * 4);
            }
        }
        u64 pa2[4][2];
#pragma unroll
        for (int i = 0; i < 4; i++) { pa2[i][0] = 0ull; pa2[i][1] = 0ull; }
#pragma unroll
        for (int k4 = 0; k4 < 8; k4++) {
            float av[4][4];
#pragma unroll
            for (int i = 0; i < 4; i++) {
                float4 a4 = *(float4*)&sx[wid * 4 + i][h * 32 + k4 * 4];
                av[i][0] = a4.x; av[i][1] = a4.y; av[i][2] = a4.z; av[i][3] = a4.w;
            }
#pragma unroll
            for (int k = 0; k < 4; k++) {
                float4 b = *(float4*)&sb.w[k4 * 4 + k][lane * 4];
                u64 b01 = pk2(b.x, b.y), b23 = pk2(b.z, b.w);
#pragma unroll
                for (int i = 0; i < 4; i++) {
                    u64 a2 = pk2(av[i][k], av[i][k]);
                    pa2[i][0] = fma2(a2, b01, pa2[i][0]);
                    pa2[i][1] = fma2(a2, b23, pa2[i][1]);
                }
            }
        }
#pragma unroll
        for (int i = 0; i < 4; i++) {
            int a = a0 + wid * 4 + i;
            if (a < NATOMS) {
                float v0, v1, v2, v3;
                up2(pa2[i][0], v0, v1);
                up2(pa2[i][1], v2, v3);
                *(float4*)&d_P[(size_t)a * 512 + h * 128 + lane * 4] =
                    make_float4(v0, v1, v2, v3);
            }
        }
    }
}

// ---------------------------------------------------------------------------
// alpha: EXACT R8/R13 form (measured 137.7/138.1 us). Do not touch.
// ---------------------------------------------------------------------------
__global__ __launch_bounds__(256, 2) void alpha_kernel(
    const float* __restrict__ rbf,  const float* __restrict__ phi,
    const float* __restrict__ pmask,
    const int*   __restrict__ idx_i, const int* __restrict__ idx_j,
    const float* __restrict__ Wf1,  const float* __restrict__ bf1,
    const float* __restrict__ Wf2,  const float* __restrict__ bf2)
{
    __shared__ __align__(16) float sW[32 * 384];   // [k][lane][12]
    __shared__ __align__(16) float sWf1[32][33];
    int tid = threadIdx.x;
    for (int idx = tid; idx < 32 * 384; idx += 256) {
        int k = idx / 384, f = idx - k * 384;
        sW[k * 384 + (f & 31) * 12 + (f >> 5)] = Wf2[idx];
    }
    for (int t = tid; t < 1024; t += 256) sWf1[t >> 5][t & 31] = Wf1[t];
    int lane = tid & 31;
    float bf1v = bf1[lane];
    float bf2v[12];
#pragma unroll
    for (int d = 0; d < 12; d++) bf2v[d] = bf2[d * 32 + lane];
    __syncthreads();

    int warp  = blockIdx.x * 8 + (tid >> 5);
    int nwarp = gridDim.x * 8;

    for (int pb = warp * 4; pb < NPAIR; pb += nwarp * 4) {
        float e[4][12], scale[4];
#pragma unroll
        for (int q = 0; q < 4; q++) {
            int p  = pb + q;
            int ii = idx_i[p], jj = idx_j[p];
            const float* Qr = &d_Q [(size_t)ii * 384 + lane];
            const float* Kr = &d_Kb[(size_t)jj * 384 + lane];
#pragma unroll
            for (int d = 0; d < 12; d++)
                e[q][d] = Qr[d * 32] * Kr[d * 32];
            float m = pmask[p];
            scale[q] = phi[p] * m * m * m * 0.17677669529663687f;
        }
        float h1[4];
#pragma unroll
        for (int q = 0; q < 4; q++) {
            float rv = rbf[(size_t)(pb + q) * 32 + lane];
            float t = bf1v;
#pragma unroll
            for (int r = 0; r < 32; r++)
                t += __shfl_sync(0xffffffffu, rv, r) * sWf1[r][lane];
            float sp = (t > 20.f) ? t : log1pf(expf(t));
            h1[q] = sp - 0.69314718055994531f;
        }
        float wacc[4][12];
#pragma unroll
        for (int q = 0; q < 4; q++)
#pragma unroll
            for (int d = 0; d < 12; d++) wacc[q][d] = bf2v[d];

#pragma unroll 4
        for (int k = 0; k < 32; k++) {
            const float4* wp = (const float4*)&sW[k * 384 + lane * 12];
            float4 w0 = wp[0], w1 = wp[1], w2 = wp[2];
#pragma unroll
            for (int q = 0; q < 4; q++) {
                float hk = __shfl_sync(0xffffffffu, h1[q], k);
                wacc[q][0]  += hk * w0.x; wacc[q][1]  += hk * w0.y;
                wacc[q][2]  += hk * w0.z; wacc[q][3]  += hk * w0.w;
                wacc[q][4]  += hk * w1.x; wacc[q][5]  += hk * w1.y;
                wacc[q][6]  += hk * w1.z; wacc[q][7]  += hk * w1.w;
                wacc[q][8]  += hk * w2.x; wacc[q][9]  += hk * w2.y;
                wacc[q][10] += hk * w2.z; wacc[q][11] += hk * w2.w;
            }
        }
#pragma unroll
        for (int q = 0; q < 4; q++) {
            float my = 0.f;
#pragma unroll
            for (int d = 0; d < 12; d++) {
                float partial = e[q][d] * wacc[q][d];
#pragma unroll
                for (int o = 16; o > 0; o >>= 1)
                    partial += __shfl_xor_sync(0xffffffffu, partial, o);
                if (lane == d) my = partial * scale[q];
            }
            if (lane < 12) d_alpha[(size_t)(pb + q) * 12 + lane] = my;
        }
    }
}

// ---------------------------------------------------------------------------
// agg: R12/R13 form (rowstart loads; measured ~58 us with rowstart).
// ---------------------------------------------------------------------------
__global__ __launch_bounds__(128) void agg_kernel(
    const int*   __restrict__ idx_j,
    const float* __restrict__ sph,   const float* __restrict__ b_out,
    float* __restrict__ out)
{
    int atom = blockIdx.x;
    int c    = threadIdx.x;
    __shared__ float sal[2][12];
    __shared__ float ssph[2][16];

    int p0 = d_rowstart[atom];
    int p1 = d_rowstart[atom + 1];

    float acc[15];
#pragma unroll
    for (int m = 0; m < 15; m++) acc[m] = 0.f;

    float pv0 = 0.f, pv1 = 0.f, pv2 = 0.f, pv3 = 0.f;
    if (p0 < p1) {
        int j0 = idx_j[p0];
        const float* Pr = &d_P[(size_t)j0 * 512 + c];
        pv0 = Pr[0]; pv1 = Pr[128]; pv2 = Pr[256]; pv3 = Pr[384];
        if (c < 12)                 sal[0][c]     = d_alpha[(size_t)p0 * 12 + c];
        else if (c >= 32 && c < 47) ssph[0][c-32] = sph[(size_t)p0 * 15 + (c - 32)];
    }
    __syncthreads();

    for (int p = p0; p < p1; p++) {
        int b  = (p - p0) & 1;
        int nb = b ^ 1;
        if (p + 1 < p1) {
            if (c < 12)                 sal[nb][c]     = d_alpha[(size_t)(p+1) * 12 + c];
            else if (c >= 32 && c < 47) ssph[nb][c-32] = sph[(size_t)(p+1) * 15 + (c - 32)];
        }
        int jn = (p + 1 < p1) ? idx_j[p + 1] : 0;
        const float* Pn = &d_P[(size_t)jn * 512 + c];
        float n0 = Pn[0], n1 = Pn[128], n2 = Pn[256], n3 = Pn[384];

        float e0 = sal[b][0]*pv0 + sal[b][1]*pv1 + sal[b][2] *pv2 + sal[b][3] *pv3;
        float e1 = sal[b][4]*pv0 + sal[b][5]*pv1 + sal[b][6] *pv2 + sal[b][7] *pv3;
        float e2 = sal[b][8]*pv0 + sal[b][9]*pv1 + sal[b][10]*pv2 + sal[b][11]*pv3;
        acc[0]  += ssph[b][0]  * e0;
        acc[1]  += ssph[b][1]  * e0;
        acc[2]  += ssph[b][2]  * e0;
        acc[3]  += ssph[b][3]  * e1;
        acc[4]  += ssph[b][4]  * e1;
        acc[5]  += ssph[b][5]  * e1;
        acc[6]  += ssph[b][6]  * e1;
        acc[7]  += ssph[b][7]  * e1;
        acc[8]  += ssph[b][8]  * e2;
        acc[9]  += ssph[b][9]  * e2;
        acc[10] += ssph[b][10] * e2;
        acc[11] += ssph[b][11] * e2;
        acc[12] += ssph[b][12] * e2;
        acc[13] += ssph[b][13] * e2;
        acc[14] += ssph[b][14] * e2;
        __syncthreads();
        pv0 = n0; pv1 = n1; pv2 = n2; pv3 = n3;
    }

    float bo = b_out[c];
#pragma unroll
    for (int m = 0; m < 15; m++)
        out[((size_t)atom * 15 + m) * 128 + c] = acc[m] + bo;
}

// ---------------------------------------------------------------------------
extern "C" void kernel_launch(void* const* d_in, const int* in_sizes, int n_in,
                              void* d_out, int out_size)
{
    const float* x     = (const float*)d_in[0];
    const float* rbf   = (const float*)d_in[1];
    const float* sph   = (const float*)d_in[2];
    const float* phi   = (const float*)d_in[3];
    const int*   idx_i = (const int*)  d_in[4];
    const int*   idx_j = (const int*)  d_in[5];
    const float* pmask = (const float*)d_in[6];
    const float* WQ    = (const float*)d_in[7];
    const float* WK    = (const float*)d_in[8];
    const float* W_in  = (const float*)d_in[9];
    const float* b_in  = (const float*)d_in[10];
    const float* Wf1   = (const float*)d_in[11];
    const float* bf1   = (const float*)d_in[12];
    const float* Wf2   = (const float*)d_in[13];
    const float* bf2   = (const float*)d_in[14];
    const float* W_out = (const float*)d_in[15];
    const float* b_out = (const float*)d_in[16];
    float* out = (float*)d_out;

    // 3 launches total: prep(+rowstart fused), alpha, agg.
    prep_kernel<<<PREP_BLOCKS + ROWSTART_BLOCKS, 256>>>(
        x, W_in, b_in, WQ, WK, W_out, idx_i);
    alpha_kernel<<<296, 256>>>(rbf, phi, pmask, idx_i, idx_j,
                               Wf1, bf1, Wf2, bf2);
    agg_kernel<<<NATOMS, 128>>>(idx_j, sph, b_out, out);
}